// round 1
// baseline (speedup 1.0000x reference)
#include <cuda_runtime.h>

// PixelAttentionModule: B=2, C=8, H=W=96, CQ=1.
// Since the QKV projection dim is 1, attention output per pixel is a smooth
// scalar function f_b(q) = sum_m v_m e^{q k_m} / sum_m e^{q k_m}.
// Strategy: (K0) compute scalar q,k,v fields + per-batch min/max;
//           (K1) tabulate f_b exactly at G grid nodes over [qmin,qmax];
//           (K2) per-pixel 4-point Lagrange cubic interpolation + residual.

#define BQ      2
#define CH      8
#define NPIX    9216            // 96*96
#define GRID_G  512

__device__ float g_q[BQ][NPIX];
__device__ float g_k[BQ][NPIX];
__device__ float g_v[BQ][NPIX];
__device__ float g_qmin[BQ], g_qmax[BQ], g_kmin[BQ], g_kmax[BQ];
__device__ float g_tab[BQ][GRID_G];

__device__ __forceinline__ float ex2f(float x) {
    float y;
    asm("ex2.approx.ftz.f32 %0, %1;" : "=f"(y) : "f"(x));
    return y;
}

__device__ __forceinline__ float warp_min(float v) {
    #pragma unroll
    for (int o = 16; o > 0; o >>= 1) v = fminf(v, __shfl_xor_sync(0xFFFFFFFFu, v, o));
    return v;
}
__device__ __forceinline__ float warp_max(float v) {
    #pragma unroll
    for (int o = 16; o > 0; o >>= 1) v = fmaxf(v, __shfl_xor_sync(0xFFFFFFFFu, v, o));
    return v;
}
__device__ __forceinline__ float warp_sum(float v) {
    #pragma unroll
    for (int o = 16; o > 0; o >>= 1) v += __shfl_xor_sync(0xFFFFFFFFu, v, o);
    return v;
}

// ---------------------------------------------------------------------------
// K0: q,k,v scalar fields + per-batch min/max of q and k. One block per batch.
// ---------------------------------------------------------------------------
__global__ void qkv_kernel(const float* __restrict__ x,
                           const float* __restrict__ Wq, const float* __restrict__ bq,
                           const float* __restrict__ Wk, const float* __restrict__ bk,
                           const float* __restrict__ Wv, const float* __restrict__ bv) {
    const int b   = blockIdx.x;
    const int tid = threadIdx.x;

    __shared__ float wq[CH], wk[CH], wv[CH];
    __shared__ float s_qmin[32], s_qmax[32], s_kmin[32], s_kmax[32];
    if (tid < CH) { wq[tid] = Wq[tid]; wk[tid] = Wk[tid]; wv[tid] = Wv[tid]; }
    __syncthreads();

    const float bqv = bq[0], bkv = bk[0], bvv = bv[0];
    const float* xb = x + (size_t)b * CH * NPIX;

    float qmin = 3.0e38f, qmax = -3.0e38f, kmin = 3.0e38f, kmax = -3.0e38f;

    for (int n = tid; n < NPIX; n += blockDim.x) {
        float q = bqv, k = bkv, v = bvv;
        #pragma unroll
        for (int c = 0; c < CH; c++) {
            float xv = xb[c * NPIX + n];
            q = fmaf(wq[c], xv, q);
            k = fmaf(wk[c], xv, k);
            v = fmaf(wv[c], xv, v);
        }
        g_q[b][n] = q; g_k[b][n] = k; g_v[b][n] = v;
        qmin = fminf(qmin, q); qmax = fmaxf(qmax, q);
        kmin = fminf(kmin, k); kmax = fmaxf(kmax, k);
    }

    qmin = warp_min(qmin); qmax = warp_max(qmax);
    kmin = warp_min(kmin); kmax = warp_max(kmax);
    const int lane = tid & 31, wid = tid >> 5;
    if (lane == 0) { s_qmin[wid] = qmin; s_qmax[wid] = qmax; s_kmin[wid] = kmin; s_kmax[wid] = kmax; }
    __syncthreads();
    if (wid == 0) {
        const int nw = (blockDim.x + 31) >> 5;
        float a = (lane < nw) ? s_qmin[lane] :  3.0e38f;
        float c = (lane < nw) ? s_qmax[lane] : -3.0e38f;
        float d = (lane < nw) ? s_kmin[lane] :  3.0e38f;
        float e = (lane < nw) ? s_kmax[lane] : -3.0e38f;
        a = warp_min(a); c = warp_max(c); d = warp_min(d); e = warp_max(e);
        if (lane == 0) { g_qmin[b] = a; g_qmax[b] = c; g_kmin[b] = d; g_kmax[b] = e; }
    }
}

// ---------------------------------------------------------------------------
// K1: table build. One block per (batch, grid node). 256 threads sum over m.
// f(qg) = sum_m v_m e^{qg*k_m - M} / sum_m e^{qg*k_m - M},  M = stability shift.
// ---------------------------------------------------------------------------
__global__ void table_kernel() {
    const int gp  = blockIdx.x;
    const int b   = gp / GRID_G;
    const int i   = gp - b * GRID_G;
    const int tid = threadIdx.x;

    const float qmin = g_qmin[b], qmax = g_qmax[b];
    const float dq   = (qmax - qmin) * (1.0f / (GRID_G - 1));
    const float qg   = qmin + dq * (float)i;
    const float M    = (qg > 0.0f) ? qg * g_kmax[b] : qg * g_kmin[b];

    const float L2E = 1.4426950408889634f;
    const float a   = qg * L2E;
    const float mb  = M * L2E;

    const float* __restrict__ kk = g_k[b];
    const float* __restrict__ vv = g_v[b];

    float S = 0.0f, T = 0.0f;
    for (int m = tid; m < NPIX; m += 256) {
        float e = ex2f(fmaf(a, kk[m], -mb));
        S += e;
        T = fmaf(vv[m], e, T);
    }

    __shared__ float sS[8], sT[8];
    S = warp_sum(S); T = warp_sum(T);
    const int lane = tid & 31, wid = tid >> 5;
    if (lane == 0) { sS[wid] = S; sT[wid] = T; }
    __syncthreads();
    if (wid == 0) {
        float s = (lane < 8) ? sS[lane] : 0.0f;
        float t = (lane < 8) ? sT[lane] : 0.0f;
        s = warp_sum(s); t = warp_sum(t);
        if (lane == 0) g_tab[b][i] = t / s;
    }
}

// ---------------------------------------------------------------------------
// K2: per-pixel 4-point Lagrange cubic interpolation of f(q_n) + residual.
// ---------------------------------------------------------------------------
__global__ void out_kernel(const float* __restrict__ x, float* __restrict__ out) {
    const int idx = blockIdx.x * blockDim.x + threadIdx.x;
    if (idx >= BQ * NPIX) return;
    const int b = idx / NPIX;
    const int n = idx - b * NPIX;

    const float qmin = g_qmin[b], qmax = g_qmax[b];
    const float dq   = (qmax - qmin) * (1.0f / (GRID_G - 1));
    const float* __restrict__ tb = g_tab[b];

    float f;
    if (dq > 0.0f) {
        float t = (g_q[b][n] - qmin) / dq;
        t = fminf(fmaxf(t, 0.0f), (float)(GRID_G - 1));
        int cell = (int)floorf(t);
        cell = min(max(cell, 1), GRID_G - 3);
        const float u = t - (float)cell;
        const float f0 = tb[cell - 1], f1 = tb[cell], f2 = tb[cell + 1], f3 = tb[cell + 2];
        // Lagrange basis on nodes {-1,0,1,2}
        const float um1 = u - 1.0f, up1 = u + 1.0f, um2 = u - 2.0f;
        const float w0 = -u   * um1 * um2 * (1.0f / 6.0f);
        const float w1 =  up1 * um1 * um2 * 0.5f;
        const float w2 = -up1 * u   * um2 * 0.5f;
        const float w3 =  up1 * u   * um1 * (1.0f / 6.0f);
        f = w0 * f0 + w1 * f1 + w2 * f2 + w3 * f3;
    } else {
        f = tb[0];
    }

    const float* xb = x   + (size_t)b * CH * NPIX + n;
    float*       ob = out + (size_t)b * CH * NPIX + n;
    #pragma unroll
    for (int c = 0; c < CH; c++)
        ob[c * NPIX] = f + xb[c * NPIX];
}

// ---------------------------------------------------------------------------
extern "C" void kernel_launch(void* const* d_in, const int* in_sizes, int n_in,
                              void* d_out, int out_size) {
    const float* x  = (const float*)d_in[0];
    const float* Wq = (const float*)d_in[1];
    const float* bq = (const float*)d_in[2];
    const float* Wk = (const float*)d_in[3];
    const float* bk = (const float*)d_in[4];
    const float* Wv = (const float*)d_in[5];
    const float* bv = (const float*)d_in[6];
    float* out = (float*)d_out;

    qkv_kernel<<<BQ, 1024>>>(x, Wq, bq, Wk, bk, Wv, bv);
    table_kernel<<<BQ * GRID_G, 256>>>();
    out_kernel<<<(BQ * NPIX + 255) / 256, 256>>>(x, out);
}

// round 2
// speedup vs baseline: 1.3469x; 1.3469x over previous
#include <cuda_runtime.h>

// PixelAttentionModule: B=2, C=8, H=W=96, CQ=1.
// Attention output per pixel is a smooth scalar function
//   f_b(q) = sum_m v_m e^{q k_m} / sum_m e^{q k_m}.
// K0: scalar q,k,v fields + per-block partial min/max (32 partials/batch).
// K1: tabulate f_b exactly at G nodes over [qmin,qmax] (partials re-reduced).
// K2: 4-point Lagrange cubic interpolation per pixel + residual.

#define BQ      2
#define CH      8
#define NPIX    9216            // 96*96
#define N4      2304            // NPIX/4
#define GRID_G  512
#define PB      32              // partial blocks per batch
#define CHUNK4  72              // N4 / PB

__device__ float g_q[BQ][NPIX];
__device__ float g_k[BQ][NPIX];
__device__ float g_v[BQ][NPIX];
__device__ float g_pqmin[BQ][PB], g_pqmax[BQ][PB];
__device__ float g_pkmin[BQ][PB], g_pkmax[BQ][PB];
__device__ float g_tab[BQ][GRID_G];

__device__ __forceinline__ float ex2f(float x) {
    float y;
    asm("ex2.approx.ftz.f32 %0, %1;" : "=f"(y) : "f"(x));
    return y;
}
__device__ __forceinline__ float warp_min(float v) {
    #pragma unroll
    for (int o = 16; o > 0; o >>= 1) v = fminf(v, __shfl_xor_sync(0xFFFFFFFFu, v, o));
    return v;
}
__device__ __forceinline__ float warp_max(float v) {
    #pragma unroll
    for (int o = 16; o > 0; o >>= 1) v = fmaxf(v, __shfl_xor_sync(0xFFFFFFFFu, v, o));
    return v;
}
__device__ __forceinline__ float warp_sum(float v) {
    #pragma unroll
    for (int o = 16; o > 0; o >>= 1) v += __shfl_xor_sync(0xFFFFFFFFu, v, o);
    return v;
}

// ---------------------------------------------------------------------------
// K0: q,k,v fields (float4) + per-block partial min/max. grid = BQ*PB x 128.
// ---------------------------------------------------------------------------
__global__ void __launch_bounds__(128) qkv_kernel(
        const float* __restrict__ x,
        const float* __restrict__ Wq, const float* __restrict__ bq,
        const float* __restrict__ Wk, const float* __restrict__ bk,
        const float* __restrict__ Wv, const float* __restrict__ bv) {
    const int b   = blockIdx.x / PB;
    const int blk = blockIdx.x - b * PB;
    const int tid = threadIdx.x;

    __shared__ float wq[CH], wk[CH], wv[CH];
    __shared__ float s_qmin[4], s_qmax[4], s_kmin[4], s_kmax[4];
    if (tid < CH) { wq[tid] = Wq[tid]; wk[tid] = Wk[tid]; wv[tid] = Wv[tid]; }
    __syncthreads();

    float qmin = 3.0e38f, qmax = -3.0e38f, kmin = 3.0e38f, kmax = -3.0e38f;

    if (tid < CHUNK4) {
        const int n4 = blk * CHUNK4 + tid;
        const float4* xb4 = (const float4*)(x + (size_t)b * CH * NPIX);

        float4 q4, k4, v4;
        {
            const float bqv = bq[0], bkv = bk[0], bvv = bv[0];
            q4 = make_float4(bqv, bqv, bqv, bqv);
            k4 = make_float4(bkv, bkv, bkv, bkv);
            v4 = make_float4(bvv, bvv, bvv, bvv);
        }
        #pragma unroll
        for (int c = 0; c < CH; c++) {
            float4 xv = xb4[c * N4 + n4];
            q4.x = fmaf(wq[c], xv.x, q4.x); q4.y = fmaf(wq[c], xv.y, q4.y);
            q4.z = fmaf(wq[c], xv.z, q4.z); q4.w = fmaf(wq[c], xv.w, q4.w);
            k4.x = fmaf(wk[c], xv.x, k4.x); k4.y = fmaf(wk[c], xv.y, k4.y);
            k4.z = fmaf(wk[c], xv.z, k4.z); k4.w = fmaf(wk[c], xv.w, k4.w);
            v4.x = fmaf(wv[c], xv.x, v4.x); v4.y = fmaf(wv[c], xv.y, v4.y);
            v4.z = fmaf(wv[c], xv.z, v4.z); v4.w = fmaf(wv[c], xv.w, v4.w);
        }
        ((float4*)g_q[b])[n4] = q4;
        ((float4*)g_k[b])[n4] = k4;
        ((float4*)g_v[b])[n4] = v4;

        qmin = fminf(fminf(q4.x, q4.y), fminf(q4.z, q4.w));
        qmax = fmaxf(fmaxf(q4.x, q4.y), fmaxf(q4.z, q4.w));
        kmin = fminf(fminf(k4.x, k4.y), fminf(k4.z, k4.w));
        kmax = fmaxf(fmaxf(k4.x, k4.y), fmaxf(k4.z, k4.w));
    }

    qmin = warp_min(qmin); qmax = warp_max(qmax);
    kmin = warp_min(kmin); kmax = warp_max(kmax);
    const int lane = tid & 31, wid = tid >> 5;
    if (lane == 0) { s_qmin[wid] = qmin; s_qmax[wid] = qmax; s_kmin[wid] = kmin; s_kmax[wid] = kmax; }
    __syncthreads();
    if (tid == 0) {
        float a = s_qmin[0], c = s_qmax[0], d = s_kmin[0], e = s_kmax[0];
        #pragma unroll
        for (int w = 1; w < 4; w++) {
            a = fminf(a, s_qmin[w]); c = fmaxf(c, s_qmax[w]);
            d = fminf(d, s_kmin[w]); e = fmaxf(e, s_kmax[w]);
        }
        g_pqmin[b][blk] = a; g_pqmax[b][blk] = c;
        g_pkmin[b][blk] = d; g_pkmax[b][blk] = e;
    }
}

// ---------------------------------------------------------------------------
// K1: table build. grid = BQ*GRID_G x 256. Each block re-reduces partials,
// then sums over m (float4): f(qg) = T/S with stability shift M.
// ---------------------------------------------------------------------------
__global__ void __launch_bounds__(256) table_kernel() {
    const int gp  = blockIdx.x;
    const int b   = gp / GRID_G;
    const int i   = gp - b * GRID_G;
    const int tid = threadIdx.x;
    const int lane = tid & 31, wid = tid >> 5;

    __shared__ float s_b[4];   // qmin, qmax, kmin, kmax
    if (wid < 4) {
        float v;
        if      (wid == 0) v = warp_min(g_pqmin[b][lane]);
        else if (wid == 1) v = warp_max(g_pqmax[b][lane]);
        else if (wid == 2) v = warp_min(g_pkmin[b][lane]);
        else               v = warp_max(g_pkmax[b][lane]);
        if (lane == 0) s_b[wid] = v;
    }
    __syncthreads();

    const float qmin = s_b[0], qmax = s_b[1];
    const float dq   = (qmax - qmin) * (1.0f / (GRID_G - 1));
    const float qg   = qmin + dq * (float)i;
    const float M    = (qg > 0.0f) ? qg * s_b[3] : qg * s_b[2];

    const float L2E = 1.4426950408889634f;
    const float a   = qg * L2E;
    const float mb  = M * L2E;

    const float4* __restrict__ kk4 = (const float4*)g_k[b];
    const float4* __restrict__ vv4 = (const float4*)g_v[b];

    float S = 0.0f, T = 0.0f;
    for (int m = tid; m < N4; m += 256) {
        float4 kv = kk4[m];
        float4 vv = vv4[m];
        float e0 = ex2f(fmaf(a, kv.x, -mb));
        float e1 = ex2f(fmaf(a, kv.y, -mb));
        float e2 = ex2f(fmaf(a, kv.z, -mb));
        float e3 = ex2f(fmaf(a, kv.w, -mb));
        S += (e0 + e1) + (e2 + e3);
        T = fmaf(vv.x, e0, T); T = fmaf(vv.y, e1, T);
        T = fmaf(vv.z, e2, T); T = fmaf(vv.w, e3, T);
    }

    __shared__ float sS[8], sT[8];
    S = warp_sum(S); T = warp_sum(T);
    if (lane == 0) { sS[wid] = S; sT[wid] = T; }
    __syncthreads();
    if (wid == 0) {
        float s = (lane < 8) ? sS[lane] : 0.0f;
        float t = (lane < 8) ? sT[lane] : 0.0f;
        s = warp_sum(s); t = warp_sum(t);
        if (lane == 0) g_tab[b][i] = t / s;
    }
}

// ---------------------------------------------------------------------------
// K2: per-pixel cubic interpolation + residual. grid = BQ*N4/128 x 128.
// Each block lies entirely within one batch (N4 % 128 == 0).
// ---------------------------------------------------------------------------
__global__ void __launch_bounds__(128) out_kernel(const float* __restrict__ x,
                                                  float* __restrict__ out) {
    const int gidx = blockIdx.x * 128 + threadIdx.x;   // index over BQ*N4
    const int b    = (blockIdx.x * 128) / N4;
    const int n4   = gidx - b * N4;
    const int tid  = threadIdx.x;
    const int lane = tid & 31, wid = tid >> 5;

    __shared__ float s_b[2];   // qmin, qmax
    if (wid < 2) {
        float v = (wid == 0) ? warp_min(g_pqmin[b][lane]) : warp_max(g_pqmax[b][lane]);
        if (lane == 0) s_b[wid] = v;
    }
    __syncthreads();

    const float qmin = s_b[0], qmax = s_b[1];
    const float dq   = (qmax - qmin) * (1.0f / (GRID_G - 1));
    const float inv_dq = (dq > 0.0f) ? (1.0f / dq) : 0.0f;
    const float* __restrict__ tb = g_tab[b];

    float4 q4 = ((const float4*)g_q[b])[n4];
    float f[4];
    const float qv[4] = {q4.x, q4.y, q4.z, q4.w};
    #pragma unroll
    for (int j = 0; j < 4; j++) {
        if (dq > 0.0f) {
            float t = (qv[j] - qmin) * inv_dq;
            t = fminf(fmaxf(t, 0.0f), (float)(GRID_G - 1));
            int cell = (int)floorf(t);
            cell = min(max(cell, 1), GRID_G - 3);
            const float u = t - (float)cell;
            const float f0 = tb[cell - 1], f1 = tb[cell], f2 = tb[cell + 1], f3 = tb[cell + 2];
            const float um1 = u - 1.0f, up1 = u + 1.0f, um2 = u - 2.0f;
            const float w0 = -u   * um1 * um2 * (1.0f / 6.0f);
            const float w1 =  up1 * um1 * um2 * 0.5f;
            const float w2 = -up1 * u   * um2 * 0.5f;
            const float w3 =  up1 * u   * um1 * (1.0f / 6.0f);
            f[j] = w0 * f0 + w1 * f1 + w2 * f2 + w3 * f3;
        } else {
            f[j] = tb[0];
        }
    }

    const float4* xb4 = (const float4*)(x   + (size_t)b * CH * NPIX);
    float4*       ob4 = (float4*)      (out + (size_t)b * CH * NPIX);
    #pragma unroll
    for (int c = 0; c < CH; c++) {
        float4 xv = xb4[c * N4 + n4];
        float4 ov;
        ov.x = f[0] + xv.x; ov.y = f[1] + xv.y;
        ov.z = f[2] + xv.z; ov.w = f[3] + xv.w;
        ob4[c * N4 + n4] = ov;
    }
}

// ---------------------------------------------------------------------------
extern "C" void kernel_launch(void* const* d_in, const int* in_sizes, int n_in,
                              void* d_out, int out_size) {
    const float* x  = (const float*)d_in[0];
    const float* Wq = (const float*)d_in[1];
    const float* bq = (const float*)d_in[2];
    const float* Wk = (const float*)d_in[3];
    const float* bk = (const float*)d_in[4];
    const float* Wv = (const float*)d_in[5];
    const float* bv = (const float*)d_in[6];
    float* out = (float*)d_out;

    qkv_kernel<<<BQ * PB, 128>>>(x, Wq, bq, Wk, bk, Wv, bv);
    table_kernel<<<BQ * GRID_G, 256>>>();
    out_kernel<<<BQ * N4 / 128, 128>>>(x, out);
}